// round 1
// baseline (speedup 1.0000x reference)
#include <cuda_runtime.h>
#include <cuda_bf16.h>
#include <cstdint>

// PolyConv: h = sum_k theta[k] * T_k, with T_0 = feat,
// T_k = T_{k-1} - D^{-1/2} A D^{-1/2}-style masked aggregation (see reference).
//
// Inputs (metadata order): feat [N*32 f32], src [E i32], dst [E i32], mask [E f32]
// Output: h [N*32 f32]

#define N_NODES 100000
#define N_EDGES 1600000
#define DFEAT   32
#define DV4     (DFEAT / 4)   // 8 float4 per node row

__device__ float g_deg[N_NODES];
__device__ float g_dinv[N_NODES];
__device__ float4 g_feat[N_NODES * DV4];
__device__ float4 g_scaled[N_NODES * DV4];
__device__ float4 g_agg[N_NODES * DV4];

__constant__ float c_theta[5] = {0.2f, -0.4f, 0.3f, -0.15f, 0.05f};

// ---------------------------------------------------------------------------
// 1) zero degree accumulator
__global__ void k_zero_deg() {
    int i = blockIdx.x * blockDim.x + threadIdx.x;
    if (i < N_NODES) g_deg[i] = 0.0f;
}

// 2) degree = segment_sum(mask, dst)
__global__ void k_deg(const int* __restrict__ dst, const float* __restrict__ mask, int E) {
    int e = blockIdx.x * blockDim.x + threadIdx.x;
    if (e < E) {
        float m = mask[e];
        int d = dst[e];
        // no-return atomic -> REDG
        atomicAdd(&g_deg[d], m);
    }
}

// 3) init: dinv, h = theta0*feat, feat_cur = feat, scaled = feat*dinv, agg = 0
__global__ void k_init(const float4* __restrict__ feat4, float4* __restrict__ h4) {
    int i = blockIdx.x * blockDim.x + threadIdx.x;
    if (i >= N_NODES * DV4) return;
    int n = i >> 3;
    float deg = g_deg[n];
    float dinv = rsqrtf(fmaxf(deg, 1.0f));
    if ((i & 7) == 0) g_dinv[n] = dinv;

    float4 f = feat4[i];
    float t0 = c_theta[0];
    float4 h;
    h.x = t0 * f.x; h.y = t0 * f.y; h.z = t0 * f.z; h.w = t0 * f.w;
    h4[i] = h;
    g_feat[i] = f;
    float4 s;
    s.x = f.x * dinv; s.y = f.y * dinv; s.z = f.z * dinv; s.w = f.w * dinv;
    g_scaled[i] = s;
    g_agg[i] = make_float4(0.0f, 0.0f, 0.0f, 0.0f);
}

// 4) edge kernel: agg[dst] += scaled[src] * mask   (8 lanes per edge, float4 each)
__global__ void __launch_bounds__(256) k_edge(const int* __restrict__ src,
                                              const int* __restrict__ dst,
                                              const float* __restrict__ mask, int E) {
    int t = blockIdx.x * blockDim.x + threadIdx.x;
    int e = t >> 3;          // edge index
    int c = t & 7;           // float4 chunk within 32-feature row
    if (e >= E) return;
    int s = __ldg(&src[e]);
    int d = __ldg(&dst[e]);
    float m = __ldg(&mask[e]);

    float4 v = g_scaled[s * DV4 + c];
    v.x *= m; v.y *= m; v.z *= m; v.w *= m;

    float4* p = &g_agg[d * DV4 + c];
    // vector reduction, no return value (REDG.v4)
    asm volatile("red.global.add.v4.f32 [%0], {%1, %2, %3, %4};"
                 :: "l"(p), "f"(v.x), "f"(v.y), "f"(v.z), "f"(v.w)
                 : "memory");
}

// 5) node update: feat -= agg*dinv; h += theta*feat; prep next iter
__global__ void k_update(float4* __restrict__ h4, float theta, int prep_next) {
    int i = blockIdx.x * blockDim.x + threadIdx.x;
    if (i >= N_NODES * DV4) return;
    int n = i >> 3;
    float dinv = g_dinv[n];

    float4 f = g_feat[i];
    float4 a = g_agg[i];
    f.x -= a.x * dinv; f.y -= a.y * dinv; f.z -= a.z * dinv; f.w -= a.w * dinv;
    g_feat[i] = f;

    float4 h = h4[i];
    h.x += theta * f.x; h.y += theta * f.y; h.z += theta * f.z; h.w += theta * f.w;
    h4[i] = h;

    if (prep_next) {
        float4 s;
        s.x = f.x * dinv; s.y = f.y * dinv; s.z = f.z * dinv; s.w = f.w * dinv;
        g_scaled[i] = s;
        g_agg[i] = make_float4(0.0f, 0.0f, 0.0f, 0.0f);
    }
}

extern "C" void kernel_launch(void* const* d_in, const int* in_sizes, int n_in,
                              void* d_out, int out_size) {
    const float* feat = (const float*)d_in[0];
    const int*   src  = (const int*)d_in[1];
    const int*   dst  = (const int*)d_in[2];
    const float* mask = (const float*)d_in[3];
    float* out = (float*)d_out;

    const int E = in_sizes[1];   // 1,600,000
    const int NV4 = N_NODES * DV4;

    const int TB = 256;

    k_zero_deg<<<(N_NODES + TB - 1) / TB, TB>>>();
    k_deg<<<(E + TB - 1) / TB, TB>>>(dst, mask, E);
    k_init<<<(NV4 + TB - 1) / TB, TB>>>((const float4*)feat, (float4*)out);

    const float theta[5] = {0.2f, -0.4f, 0.3f, -0.15f, 0.05f};
    int edge_blocks = (E * 8 + TB - 1) / TB;
    int node_blocks = (NV4 + TB - 1) / TB;

    for (int k = 1; k <= 4; ++k) {
        k_edge<<<edge_blocks, TB>>>(src, dst, mask, E);
        k_update<<<node_blocks, TB>>>((float4*)out, theta[k], (k < 4) ? 1 : 0);
    }
}

// round 3
// speedup vs baseline: 1.4375x; 1.4375x over previous
#include <cuda_runtime.h>
#include <cuda_bf16.h>
#include <cstdint>

// PolyConv via per-launch CSR build + atomic-free fused iterations.
// Inputs: feat [N*32 f32], src [E i32], dst [E i32], mask [E f32]
// Output: h [N*32 f32]

#define N_NODES 100000
#define N_EDGES 1600000
#define DFEAT   32
#define DV4     (DFEAT / 4)        // 8 float4 chunks per node row
#define NV4     (N_NODES * DV4)

#define SCAN_B  1024
#define N_SBLK  ((N_NODES + SCAN_B - 1) / SCAN_B)   // 98

// ---- scratch (static __device__, no allocation) ----
__device__ int    g_cnt[N_NODES];       // in-degree (edge count)
__device__ float  g_degf[N_NODES];      // mask-sum degree
__device__ float  g_dinv[N_NODES];
__device__ int    g_row[N_NODES + 1];   // CSR row starts (exclusive scan), +1 for end
__device__ int    g_cursor[N_NODES];    // scatter cursors
__device__ int    g_bsum[N_SBLK];       // scan block sums
__device__ int2   g_edges[N_EDGES];     // CSR edges: {src, mask_bits} grouped by dst
__device__ float4 g_feat[NV4];
__device__ float4 g_scaledA[NV4];
__device__ float4 g_scaledB[NV4];

// ---------------------------------------------------------------------------
__global__ void k_zero() {
    int i = blockIdx.x * blockDim.x + threadIdx.x;
    if (i < N_NODES) { g_cnt[i] = 0; g_degf[i] = 0.0f; }
}

// histogram: edge count + mask-sum per dst
__global__ void k_hist(const int* __restrict__ dst, const float* __restrict__ mask, int E) {
    int e = blockIdx.x * blockDim.x + threadIdx.x;
    if (e < E) {
        int d = dst[e];
        atomicAdd(&g_cnt[d], 1);
        atomicAdd(&g_degf[d], mask[e]);
    }
}

// exclusive scan, stage 1: per-block scan of g_cnt -> g_row, block totals -> g_bsum
__global__ void k_scan1() {
    __shared__ int sh[SCAN_B];
    int t = threadIdx.x;
    int gid = blockIdx.x * SCAN_B + t;
    int v = (gid < N_NODES) ? g_cnt[gid] : 0;
    sh[t] = v;
    __syncthreads();
    for (int off = 1; off < SCAN_B; off <<= 1) {
        int x = (t >= off) ? sh[t - off] : 0;
        __syncthreads();
        sh[t] += x;
        __syncthreads();
    }
    int incl = sh[t];
    if (gid < N_NODES) g_row[gid] = incl - v;          // exclusive within block
    if (t == SCAN_B - 1) g_bsum[blockIdx.x] = incl;    // block total
}

// stage 2: exclusive scan of the block sums (single block of 128 >= N_SBLK)
__global__ void k_scan2() {
    __shared__ int sh[128];
    int t = threadIdx.x;
    int v = (t < N_SBLK) ? g_bsum[t] : 0;
    sh[t] = v;
    __syncthreads();
    for (int off = 1; off < 128; off <<= 1) {
        int x = (t >= off) ? sh[t - off] : 0;
        __syncthreads();
        sh[t] += x;
        __syncthreads();
    }
    if (t < N_SBLK) g_bsum[t] = sh[t] - v;             // exclusive
}

// stage 3: add block offsets, init cursor, compute dinv, set row[N] = E
__global__ void k_scan3(int E) {
    int i = blockIdx.x * blockDim.x + threadIdx.x;
    if (i >= N_NODES) return;
    int r = g_row[i] + g_bsum[i / SCAN_B];
    g_row[i] = r;
    g_cursor[i] = r;
    g_dinv[i] = rsqrtf(fmaxf(g_degf[i], 1.0f));
    if (i == 0) g_row[N_NODES] = E;
}

// scatter edges into CSR order (grouped by dst)
__global__ void k_scatter(const int* __restrict__ src, const int* __restrict__ dst,
                          const float* __restrict__ mask, int E) {
    int e = blockIdx.x * blockDim.x + threadIdx.x;
    if (e >= E) return;
    int d = dst[e];
    int pos = atomicAdd(&g_cursor[d], 1);
    g_edges[pos] = make_int2(src[e], __float_as_int(mask[e]));
}

// init: h = theta0*feat; feat_cur = feat; scaledA = feat*dinv
__global__ void k_init(const float4* __restrict__ feat4, float4* __restrict__ h4,
                       float theta0) {
    int i = blockIdx.x * blockDim.x + threadIdx.x;
    if (i >= NV4) return;
    int n = i >> 3;
    float dinv = g_dinv[n];
    float4 f = feat4[i];
    float4 h;
    h.x = theta0 * f.x; h.y = theta0 * f.y; h.z = theta0 * f.z; h.w = theta0 * f.w;
    h4[i] = h;
    g_feat[i] = f;
    float4 s;
    s.x = f.x * dinv; s.y = f.y * dinv; s.z = f.z * dinv; s.w = f.w * dinv;
    g_scaledA[i] = s;
}

// fused iteration: per-node gather-aggregate (atomic-free) + update + h accumulate.
// 8 threads per node (one float4 chunk each); 256-thread block = 32 nodes.
// a_to_b selects the ping-pong direction (device symbols referenced in device code only).
__global__ void __launch_bounds__(256)
k_iter_sel(float4* __restrict__ h4, float theta, int write_next, int a_to_b) {
    const float4* __restrict__ scaled_in  = a_to_b ? g_scaledA : g_scaledB;
    float4* __restrict__       scaled_out = a_to_b ? g_scaledB : g_scaledA;

    int t = threadIdx.x;
    int n = blockIdx.x * 32 + (t >> 3);
    if (n >= N_NODES) return;
    int c = t & 7;

    int base = g_row[n];
    int end  = g_row[n + 1];
    float4 acc = make_float4(0.0f, 0.0f, 0.0f, 0.0f);
    for (int j = base; j < end; ++j) {
        int2 ed = g_edges[j];                 // same addr across 8 lanes -> broadcast
        float m = __int_as_float(ed.y);
        float4 v = scaled_in[ed.x * DV4 + c]; // 8 lanes cover one 128B row
        acc.x += v.x * m; acc.y += v.y * m; acc.z += v.z * m; acc.w += v.w * m;
    }

    int i = n * DV4 + c;
    float dinv = g_dinv[n];
    float4 f = g_feat[i];
    f.x -= acc.x * dinv; f.y -= acc.y * dinv; f.z -= acc.z * dinv; f.w -= acc.w * dinv;
    g_feat[i] = f;

    float4 h = h4[i];
    h.x += theta * f.x; h.y += theta * f.y; h.z += theta * f.z; h.w += theta * f.w;
    h4[i] = h;

    if (write_next) {
        float4 s;
        s.x = f.x * dinv; s.y = f.y * dinv; s.z = f.z * dinv; s.w = f.w * dinv;
        scaled_out[i] = s;
    }
}

extern "C" void kernel_launch(void* const* d_in, const int* in_sizes, int n_in,
                              void* d_out, int out_size) {
    const float* feat = (const float*)d_in[0];
    const int*   src  = (const int*)d_in[1];
    const int*   dst  = (const int*)d_in[2];
    const float* mask = (const float*)d_in[3];
    float* out = (float*)d_out;

    const int E = in_sizes[1];
    const int TB = 256;

    // --- CSR build ---
    k_zero<<<(N_NODES + TB - 1) / TB, TB>>>();
    k_hist<<<(E + TB - 1) / TB, TB>>>(dst, mask, E);
    k_scan1<<<N_SBLK, SCAN_B>>>();
    k_scan2<<<1, 128>>>();
    k_scan3<<<(N_NODES + TB - 1) / TB, TB>>>(E);
    k_scatter<<<(E + TB - 1) / TB, TB>>>(src, dst, mask, E);

    // --- init ---
    k_init<<<(NV4 + TB - 1) / TB, TB>>>((const float4*)feat, (float4*)out, 0.2f);

    // --- 4 fused iterations, ping-pong scaled buffers ---
    const float theta[5] = {0.2f, -0.4f, 0.3f, -0.15f, 0.05f};
    int iter_blocks = (N_NODES + 31) / 32;

    for (int k = 1; k <= 4; ++k) {
        k_iter_sel<<<iter_blocks, TB>>>((float4*)out, theta[k], (k < 4) ? 1 : 0, k & 1);
    }
}

// round 4
// speedup vs baseline: 1.5907x; 1.1065x over previous
#include <cuda_runtime.h>
#include <cuda_bf16.h>
#include <cstdint>

// PolyConv: per-launch CSR build + atomic-free fused iterations (scaled-only state).
// Inputs: feat [N*32 f32], src [E i32], dst [E i32], mask [E f32]
// Output: h [N*32 f32]

#define N_NODES 100000
#define N_EDGES 1600000
#define DFEAT   32
#define DV4     (DFEAT / 4)        // 8 float4 chunks per node row
#define NV4     (N_NODES * DV4)

#define SCAN_B  1024
#define N_SBLK  ((N_NODES + SCAN_B - 1) / SCAN_B)   // 98

// ---- scratch (static __device__, no allocation) ----
__device__ int    g_cnt[N_NODES];        // in-degree (edge count)
__device__ float  g_degf[N_NODES];       // mask-sum degree
__device__ int    g_row[N_NODES + 1];    // CSR row starts
__device__ int    g_cursor[N_NODES];     // scatter cursors
__device__ int    g_bsum[N_SBLK];        // scan block sums (inclusive per block)
__device__ float2 g_fac[N_NODES];        // {dinv^2, sqrt(max(deg,1))}
__device__ int2   g_edges[N_EDGES];      // CSR edges: {src, mask_bits} grouped by dst
__device__ float4 g_scaledA[NV4];
__device__ float4 g_scaledB[NV4];

// ---------------------------------------------------------------------------
__global__ void k_zero() {
    int i = blockIdx.x * blockDim.x + threadIdx.x;
    if (i < N_NODES) { g_cnt[i] = 0; g_degf[i] = 0.0f; }
}

// histogram: edge count + mask-sum per dst
__global__ void k_hist(const int* __restrict__ dst, const float* __restrict__ mask, int E) {
    int e = blockIdx.x * blockDim.x + threadIdx.x;
    if (e < E) {
        int d = dst[e];
        atomicAdd(&g_cnt[d], 1);
        atomicAdd(&g_degf[d], mask[e]);
    }
}

// scan stage 1: per-block exclusive scan of g_cnt -> g_row, inclusive totals -> g_bsum
__global__ void k_scan1() {
    __shared__ int sh[SCAN_B];
    int t = threadIdx.x;
    int gid = blockIdx.x * SCAN_B + t;
    int v = (gid < N_NODES) ? g_cnt[gid] : 0;
    sh[t] = v;
    __syncthreads();
    for (int off = 1; off < SCAN_B; off <<= 1) {
        int x = (t >= off) ? sh[t - off] : 0;
        __syncthreads();
        sh[t] += x;
        __syncthreads();
    }
    int incl = sh[t];
    if (gid < N_NODES) g_row[gid] = incl - v;          // exclusive within block
    if (t == SCAN_B - 1) g_bsum[blockIdx.x] = incl;    // block total
}

// scan stage 2+3 merged: every block redundantly scans the 98 block sums in
// shared, applies its own offset, inits cursor, computes node factors.
__global__ void k_scan23(int E) {
    __shared__ int sb[128];
    int t = threadIdx.x;
    if (t < 128) sb[t] = (t < N_SBLK) ? g_bsum[t] : 0;
    __syncthreads();
    for (int off = 1; off < 128; off <<= 1) {
        int x = (t >= off && t < 128) ? sb[t - off] : 0;
        __syncthreads();
        if (t < 128) sb[t] += x;
        __syncthreads();
    }
    // sb now holds inclusive sums; block b's exclusive offset = sb[b-1]
    int prefix = (blockIdx.x > 0) ? sb[blockIdx.x - 1] : 0;

    int gid = blockIdx.x * SCAN_B + t;
    if (gid < N_NODES) {
        int r = g_row[gid] + prefix;
        g_row[gid] = r;
        g_cursor[gid] = r;
        float deg = fmaxf(g_degf[gid], 1.0f);
        float dinv = rsqrtf(deg);
        g_fac[gid] = make_float2(dinv * dinv, deg * dinv);  // {dinv^2, sqrt(deg)}
    }
    if (gid == 0) g_row[N_NODES] = E;
}

// scatter edges into CSR order (grouped by dst)
__global__ void k_scatter(const int* __restrict__ src, const int* __restrict__ dst,
                          const float* __restrict__ mask, int E) {
    int e = blockIdx.x * blockDim.x + threadIdx.x;
    if (e >= E) return;
    int d = dst[e];
    int pos = atomicAdd(&g_cursor[d], 1);
    g_edges[pos] = make_int2(src[e], __float_as_int(mask[e]));
}

// init: scaledA = feat * dinv   (dinv recomputed from degf; cheap)
__global__ void k_init(const float4* __restrict__ feat4) {
    int i = blockIdx.x * blockDim.x + threadIdx.x;
    if (i >= NV4) return;
    int n = i >> 3;
    float dinv = rsqrtf(fmaxf(g_degf[n], 1.0f));
    float4 f = feat4[i];
    float4 s;
    s.x = f.x * dinv; s.y = f.y * dinv; s.z = f.z * dinv; s.w = f.w * dinv;
    g_scaledA[i] = s;
}

// fused iteration: gather-aggregate (atomic-free) over CSR in-edges, update
// scaled, accumulate h. 8 threads per node (one float4 chunk each).
// flags: bit0 = write scaled_out, bit1 = first iteration (h pure write).
__global__ void __launch_bounds__(256)
k_iter_sel(float4* __restrict__ h4, float theta, float theta_prev,
           int flags, int a_to_b) {
    const float4* __restrict__ scaled_in  = a_to_b ? g_scaledA : g_scaledB;
    float4* __restrict__       scaled_out = a_to_b ? g_scaledB : g_scaledA;

    int t = threadIdx.x;
    int n = blockIdx.x * 32 + (t >> 3);
    if (n >= N_NODES) return;
    int c = t & 7;

    int base = g_row[n];
    int end  = g_row[n + 1];

    float4 acc = make_float4(0.0f, 0.0f, 0.0f, 0.0f);
    int j = base;
    // 4-way unrolled gather: 4 independent row loads in flight per iteration
    for (; j + 4 <= end; j += 4) {
        int2 e0 = g_edges[j + 0];
        int2 e1 = g_edges[j + 1];
        int2 e2 = g_edges[j + 2];
        int2 e3 = g_edges[j + 3];
        float4 v0 = scaled_in[e0.x * DV4 + c];
        float4 v1 = scaled_in[e1.x * DV4 + c];
        float4 v2 = scaled_in[e2.x * DV4 + c];
        float4 v3 = scaled_in[e3.x * DV4 + c];
        float m0 = __int_as_float(e0.y), m1 = __int_as_float(e1.y);
        float m2 = __int_as_float(e2.y), m3 = __int_as_float(e3.y);
        acc.x += v0.x * m0 + v1.x * m1 + v2.x * m2 + v3.x * m3;
        acc.y += v0.y * m0 + v1.y * m1 + v2.y * m2 + v3.y * m3;
        acc.z += v0.z * m0 + v1.z * m1 + v2.z * m2 + v3.z * m3;
        acc.w += v0.w * m0 + v1.w * m1 + v2.w * m2 + v3.w * m3;
    }
    for (; j < end; ++j) {
        int2 ed = g_edges[j];
        float m = __int_as_float(ed.y);
        float4 v = scaled_in[ed.x * DV4 + c];
        acc.x += v.x * m; acc.y += v.y * m; acc.z += v.z * m; acc.w += v.w * m;
    }

    int i = n * DV4 + c;
    float2 fac = g_fac[n];            // {dinv^2, sqrt(deg)}
    float dinv2 = fac.x, rsq = fac.y;

    float4 s_old = scaled_in[i];
    float4 s_new;
    s_new.x = s_old.x - acc.x * dinv2;
    s_new.y = s_old.y - acc.y * dinv2;
    s_new.z = s_old.z - acc.z * dinv2;
    s_new.w = s_old.w - acc.w * dinv2;

    float tr = theta * rsq;
    float4 h;
    if (flags & 2) {
        // first iteration: h = theta_prev*feat + theta*T1  (feat = s_old*rsq)
        float tpr = theta_prev * rsq;
        h.x = tpr * s_old.x + tr * s_new.x;
        h.y = tpr * s_old.y + tr * s_new.y;
        h.z = tpr * s_old.z + tr * s_new.z;
        h.w = tpr * s_old.w + tr * s_new.w;
    } else {
        h = h4[i];
        h.x += tr * s_new.x; h.y += tr * s_new.y;
        h.z += tr * s_new.z; h.w += tr * s_new.w;
    }
    h4[i] = h;

    if (flags & 1) scaled_out[i] = s_new;
}

extern "C" void kernel_launch(void* const* d_in, const int* in_sizes, int n_in,
                              void* d_out, int out_size) {
    const float* feat = (const float*)d_in[0];
    const int*   src  = (const int*)d_in[1];
    const int*   dst  = (const int*)d_in[2];
    const float* mask = (const float*)d_in[3];
    float* out = (float*)d_out;

    const int E = in_sizes[1];
    const int TB = 256;

    // --- CSR build ---
    k_zero<<<(N_NODES + TB - 1) / TB, TB>>>();
    k_hist<<<(E + TB - 1) / TB, TB>>>(dst, mask, E);
    k_scan1<<<N_SBLK, SCAN_B>>>();
    k_scan23<<<N_SBLK, SCAN_B>>>(E);
    k_scatter<<<(E + TB - 1) / TB, TB>>>(src, dst, mask, E);

    // --- init scaled ---
    k_init<<<(NV4 + TB - 1) / TB, TB>>>((const float4*)feat);

    // --- 4 fused iterations, ping-pong scaled buffers ---
    const float theta[5] = {0.2f, -0.4f, 0.3f, -0.15f, 0.05f};
    int iter_blocks = (N_NODES + 31) / 32;

    for (int k = 1; k <= 4; ++k) {
        int flags = ((k < 4) ? 1 : 0) | ((k == 1) ? 2 : 0);
        k_iter_sel<<<iter_blocks, TB>>>((float4*)out, theta[k], theta[0],
                                        flags, k & 1);
    }
}

// round 5
// speedup vs baseline: 1.6158x; 1.0158x over previous
#include <cuda_runtime.h>
#include <cuda_fp16.h>
#include <cstdint>

// PolyConv: CSR build + atomic-free fused iterations.
// State in fp32 (in-place), gather path in fp16 (ping-pong copies).
// Inputs: feat [N*32 f32], src [E i32], dst [E i32], mask [E f32]
// Output: h [N*32 f32]

#define N_NODES 100000
#define N_EDGES 1600000
#define DFEAT   32
#define DV4     (DFEAT / 4)        // 8 float4 per node row
#define NV4     (N_NODES * DV4)
#define NH4     (N_NODES * 4)      // 4 uint4 (8 halves each) per node row

#define SCAN_B  1024
#define N_SBLK  ((N_NODES + SCAN_B - 1) / SCAN_B)   // 98

// ---- scratch (static __device__, no allocation) ----
__device__ int    g_cnt[N_NODES];
__device__ float  g_degf[N_NODES];
__device__ int    g_row[N_NODES + 1];
__device__ int    g_cursor[N_NODES];
__device__ int    g_bsum[N_SBLK];
__device__ float2 g_fac[N_NODES];        // {dinv^2, sqrt(max(deg,1))}
__device__ int2   g_edges[N_EDGES];      // CSR: {src, mask_bits} grouped by dst
__device__ float4 g_scaled[NV4];         // fp32 state, in-place
__device__ uint4  g_halfA[NH4];          // fp16 gather copy (ping)
__device__ uint4  g_halfB[NH4];          // fp16 gather copy (pong)

static __device__ __forceinline__ unsigned h2u(__half2 h) {
    return *reinterpret_cast<unsigned*>(&h);
}

// ---------------------------------------------------------------------------
__global__ void k_zero() {
    int i = blockIdx.x * blockDim.x + threadIdx.x;
    if (i < N_NODES) { g_cnt[i] = 0; g_degf[i] = 0.0f; }
}

__global__ void k_hist(const int* __restrict__ dst, const float* __restrict__ mask, int E) {
    int e = blockIdx.x * blockDim.x + threadIdx.x;
    if (e < E) {
        int d = dst[e];
        atomicAdd(&g_cnt[d], 1);
        atomicAdd(&g_degf[d], mask[e]);
    }
}

// scan stage 1: per-block exclusive scan of g_cnt -> g_row, block totals -> g_bsum
__global__ void k_scan1() {
    __shared__ int sh[SCAN_B];
    int t = threadIdx.x;
    int gid = blockIdx.x * SCAN_B + t;
    int v = (gid < N_NODES) ? g_cnt[gid] : 0;
    sh[t] = v;
    __syncthreads();
    for (int off = 1; off < SCAN_B; off <<= 1) {
        int x = (t >= off) ? sh[t - off] : 0;
        __syncthreads();
        sh[t] += x;
        __syncthreads();
    }
    int incl = sh[t];
    if (gid < N_NODES) g_row[gid] = incl - v;
    if (t == SCAN_B - 1) g_bsum[blockIdx.x] = incl;
}

// stage 2+3: each block warp-reduces the prior block totals (one number),
// applies offset, inits cursor, computes node factors.
__global__ void k_scan23(int E) {
    __shared__ int s_prefix;
    int t = threadIdx.x;
    if (t < 32) {
        int sum = 0;
        for (int b = t; b < N_SBLK; b += 32)
            if (b < (int)blockIdx.x) sum += g_bsum[b];
        #pragma unroll
        for (int o = 16; o; o >>= 1) sum += __shfl_xor_sync(0xFFFFFFFFu, sum, o);
        if (t == 0) s_prefix = sum;
    }
    __syncthreads();
    int prefix = s_prefix;

    int gid = blockIdx.x * SCAN_B + t;
    if (gid < N_NODES) {
        int r = g_row[gid] + prefix;
        g_row[gid] = r;
        g_cursor[gid] = r;
        float deg = fmaxf(g_degf[gid], 1.0f);
        float dinv = rsqrtf(deg);
        g_fac[gid] = make_float2(dinv * dinv, deg * dinv);  // {dinv^2, sqrt(deg)}
    }
    if (gid == 0) g_row[N_NODES] = E;
}

__global__ void k_scatter(const int* __restrict__ src, const int* __restrict__ dst,
                          const float* __restrict__ mask, int E) {
    int e = blockIdx.x * blockDim.x + threadIdx.x;
    if (e >= E) return;
    int d = dst[e];
    int pos = atomicAdd(&g_cursor[d], 1);
    g_edges[pos] = make_int2(src[e], __float_as_int(mask[e]));
}

// init: scaled = feat*dinv (fp32) + fp16 copy into g_halfA.
// One thread per quarter-row (8 features = 2 float4 = 1 uint4 of halves).
__global__ void k_init(const float4* __restrict__ feat4) {
    int i = blockIdx.x * blockDim.x + threadIdx.x;
    if (i >= NH4) return;
    int n = i >> 2;
    int c = i & 3;
    float dinv = rsqrtf(fmaxf(g_degf[n], 1.0f));
    int i0 = n * DV4 + c * 2;
    float4 f0 = feat4[i0], f1 = feat4[i0 + 1];
    float4 s0, s1;
    s0.x = f0.x * dinv; s0.y = f0.y * dinv; s0.z = f0.z * dinv; s0.w = f0.w * dinv;
    s1.x = f1.x * dinv; s1.y = f1.y * dinv; s1.z = f1.z * dinv; s1.w = f1.w * dinv;
    g_scaled[i0] = s0;
    g_scaled[i0 + 1] = s1;
    uint4 hp;
    hp.x = h2u(__floats2half2_rn(s0.x, s0.y));
    hp.y = h2u(__floats2half2_rn(s0.z, s0.w));
    hp.z = h2u(__floats2half2_rn(s1.x, s1.y));
    hp.w = h2u(__floats2half2_rn(s1.z, s1.w));
    g_halfA[i] = hp;
}

// fused iteration: gather (fp16) + aggregate + in-place fp32 state update +
// h accumulate + fp16 copy write. 4 lanes per node, 8 features per lane.
// flags: bit0 = write next fp16 copy, bit1 = first iteration (h pure write).
__global__ void __launch_bounds__(256)
k_iter(float4* __restrict__ h4, float theta, float theta0, int flags, int a_to_b) {
    const uint4* __restrict__ gin  = a_to_b ? g_halfA : g_halfB;
    uint4* __restrict__       gout = a_to_b ? g_halfB : g_halfA;

    int t = threadIdx.x;
    int n = blockIdx.x * 64 + (t >> 2);
    if (n >= N_NODES) return;
    int c = t & 3;

    int base = g_row[n];
    int end  = g_row[n + 1];

    float a0 = 0.f, a1 = 0.f, a2 = 0.f, a3 = 0.f;
    float a4 = 0.f, a5 = 0.f, a6 = 0.f, a7 = 0.f;

    #pragma unroll 4
    for (int j = base; j < end; ++j) {
        int2 ed = g_edges[j];                 // broadcast across 4 lanes
        float m = __int_as_float(ed.y);
        uint4 v = gin[ed.x * 4 + c];          // 16B of fp16; 4 lanes = 64B row
        float2 f;
        f = __half22float2(*reinterpret_cast<__half2*>(&v.x)); a0 += f.x * m; a1 += f.y * m;
        f = __half22float2(*reinterpret_cast<__half2*>(&v.y)); a2 += f.x * m; a3 += f.y * m;
        f = __half22float2(*reinterpret_cast<__half2*>(&v.z)); a4 += f.x * m; a5 += f.y * m;
        f = __half22float2(*reinterpret_cast<__half2*>(&v.w)); a6 += f.x * m; a7 += f.y * m;
    }

    float2 fac = g_fac[n];
    float dinv2 = fac.x, rsq = fac.y;

    int i0 = n * DV4 + c * 2;
    float4 s0 = g_scaled[i0], s1 = g_scaled[i0 + 1];
    float4 o0 = s0, o1 = s1;               // s_old, needed only for first iter
    s0.x -= a0 * dinv2; s0.y -= a1 * dinv2; s0.z -= a2 * dinv2; s0.w -= a3 * dinv2;
    s1.x -= a4 * dinv2; s1.y -= a5 * dinv2; s1.z -= a6 * dinv2; s1.w -= a7 * dinv2;
    g_scaled[i0] = s0;
    g_scaled[i0 + 1] = s1;

    float tr = theta * rsq;
    float4 h0, h1;
    if (flags & 2) {
        float tpr = theta0 * rsq;          // h = theta0*feat + theta1*T1
        h0.x = tpr * o0.x + tr * s0.x; h0.y = tpr * o0.y + tr * s0.y;
        h0.z = tpr * o0.z + tr * s0.z; h0.w = tpr * o0.w + tr * s0.w;
        h1.x = tpr * o1.x + tr * s1.x; h1.y = tpr * o1.y + tr * s1.y;
        h1.z = tpr * o1.z + tr * s1.z; h1.w = tpr * o1.w + tr * s1.w;
    } else {
        h0 = h4[i0]; h1 = h4[i0 + 1];
        h0.x += tr * s0.x; h0.y += tr * s0.y; h0.z += tr * s0.z; h0.w += tr * s0.w;
        h1.x += tr * s1.x; h1.y += tr * s1.y; h1.z += tr * s1.z; h1.w += tr * s1.w;
    }
    h4[i0] = h0;
    h4[i0 + 1] = h1;

    if (flags & 1) {
        uint4 hp;
        hp.x = h2u(__floats2half2_rn(s0.x, s0.y));
        hp.y = h2u(__floats2half2_rn(s0.z, s0.w));
        hp.z = h2u(__floats2half2_rn(s1.x, s1.y));
        hp.w = h2u(__floats2half2_rn(s1.z, s1.w));
        gout[n * 4 + c] = hp;
    }
}

extern "C" void kernel_launch(void* const* d_in, const int* in_sizes, int n_in,
                              void* d_out, int out_size) {
    const float* feat = (const float*)d_in[0];
    const int*   src  = (const int*)d_in[1];
    const int*   dst  = (const int*)d_in[2];
    const float* mask = (const float*)d_in[3];
    float* out = (float*)d_out;

    const int E = in_sizes[1];
    const int TB = 256;

    // --- CSR build ---
    k_zero<<<(N_NODES + TB - 1) / TB, TB>>>();
    k_hist<<<(E + TB - 1) / TB, TB>>>(dst, mask, E);
    k_scan1<<<N_SBLK, SCAN_B>>>();
    k_scan23<<<N_SBLK, SCAN_B>>>(E);
    k_scatter<<<(E + TB - 1) / TB, TB>>>(src, dst, mask, E);

    // --- init ---
    k_init<<<(NH4 + TB - 1) / TB, TB>>>((const float4*)feat);

    // --- 4 fused iterations ---
    const float theta[5] = {0.2f, -0.4f, 0.3f, -0.15f, 0.05f};
    int iter_blocks = (N_NODES + 63) / 64;

    for (int k = 1; k <= 4; ++k) {
        int flags = ((k < 4) ? 1 : 0) | ((k == 1) ? 2 : 0);
        k_iter<<<iter_blocks, TB>>>((float4*)out, theta[k], theta[0], flags, k & 1);
    }
}